// round 1
// baseline (speedup 1.0000x reference)
#include <cuda_runtime.h>

#define B_  16
#define T_  2048
#define E_  512
#define H_  4
#define C_  3
#define NT  (B_ * T_)   // 32768 tokens

// Scratch for attention output v[NT][E] (64 MB, static device global — allowed)
__device__ float g_v[(size_t)NT * E_];

// ---------------------------------------------------------------------------
// Kernel A: embed gather + windowed multi-head positional attention -> g_v
// One block = 256 threads handles 32 tokens (each warp: 4 tokens).
// pos (4*512*3 floats = 24KB) cached in smem once per block.
// ---------------------------------------------------------------------------
__global__ __launch_bounds__(256) void attn_kernel(const int* __restrict__ tokens,
                                                   const float* __restrict__ table,
                                                   const float* __restrict__ pos) {
    __shared__ float pos_s[H_ * E_ * C_];  // pos[h][e][c], 6144 floats
    int tid = threadIdx.x;
    for (int i = tid; i < H_ * E_ * C_; i += 256) pos_s[i] = pos[i];
    __syncthreads();

    int warp = tid >> 5, lane = tid & 31;
    int base = blockIdx.x * 32 + warp * 4;

    for (int it = 0; it < 4; ++it) {
        int g = base + it;
        int t = g & (T_ - 1);

        int rows[3];
        rows[2] = tokens[g];
        rows[1] = (t >= 1) ? tokens[g - 1] : -1;
        rows[0] = (t >= 2) ? tokens[g - 2] : -1;

        // Each lane owns e = lane + 32*j, j=0..15 (coalesced loads)
        float x[3][16];
        #pragma unroll
        for (int c = 0; c < 3; ++c) {
            if (rows[c] >= 0) {
                const float* rp = table + (size_t)rows[c] * E_;
                #pragma unroll
                for (int j = 0; j < 16; ++j) x[c][j] = rp[lane + j * 32];
            } else {
                #pragma unroll
                for (int j = 0; j < 16; ++j) x[c][j] = 0.0f;
            }
        }

        // Partial scores s[h][c] = sum_e x_win[c][e] * pos[h][e][c]
        float s[12];
        #pragma unroll
        for (int i = 0; i < 12; ++i) s[i] = 0.0f;
        #pragma unroll
        for (int j = 0; j < 16; ++j) {
            int e = lane + j * 32;
            #pragma unroll
            for (int h = 0; h < 4; ++h) {
                const float* pp = pos_s + h * (E_ * C_) + e * C_;  // stride-3: conflict-free
                #pragma unroll
                for (int c = 0; c < 3; ++c)
                    s[h * 3 + c] = fmaf(x[c][j], pp[c], s[h * 3 + c]);
            }
        }
        // Warp butterfly reduce all 12 partial dots
        #pragma unroll
        for (int off = 16; off > 0; off >>= 1) {
            #pragma unroll
            for (int i = 0; i < 12; ++i)
                s[i] += __shfl_xor_sync(0xffffffffu, s[i], off);
        }

        // out[e] = sum_{h,c} w[h,c] * x_win[c][e] / 12  => coeff[c] = sum_h w[h,c] / 12
        float coeff[3];
        #pragma unroll
        for (int c = 0; c < 3; ++c)
            coeff[c] = (s[0 * 3 + c] + s[1 * 3 + c] + s[2 * 3 + c] + s[3 * 3 + c]) * (1.0f / 12.0f);

        float* vp = g_v + (size_t)g * E_;
        #pragma unroll
        for (int j = 0; j < 16; ++j) {
            float v = coeff[0] * x[0][j] + coeff[1] * x[1][j] + coeff[2] * x[2][j];
            vp[lane + j * 32] = v;
        }
    }
}

// ---------------------------------------------------------------------------
// Kernel B: Y = V @ W^T + bias  (M=32768, N=512, K=512)  classic fp32 SGEMM
// Block tile 128x128, BK=16, 256 threads, 8x8 per-thread microtile.
// ---------------------------------------------------------------------------
#define BM 128
#define BN 128
#define BK 16

__global__ __launch_bounds__(256) void ffn_kernel(const float* __restrict__ W,
                                                  const float* __restrict__ bias,
                                                  float* __restrict__ out) {
    __shared__ float As[BK][BM];
    __shared__ float Bs[BK][BN];
    const float* V = g_v;

    int tid  = threadIdx.x;
    int row0 = blockIdx.y * BM;
    int col0 = blockIdx.x * BN;
    int tm   = (tid / 16) * 8;
    int tn   = (tid % 16) * 8;

    float acc[8][8];
    #pragma unroll
    for (int i = 0; i < 8; ++i)
        #pragma unroll
        for (int j = 0; j < 8; ++j) acc[i][j] = 0.0f;

    for (int k0 = 0; k0 < E_; k0 += BK) {
        #pragma unroll
        for (int i = 0; i < 2; ++i) {
            int linear = tid + i * 256;      // 0..511
            int m  = linear >> 2;            // 0..127
            int k4 = (linear & 3) * 4;       // 0,4,8,12
            float4 va = *(const float4*)(V + (size_t)(row0 + m) * E_ + k0 + k4);
            As[k4 + 0][m] = va.x; As[k4 + 1][m] = va.y;
            As[k4 + 2][m] = va.z; As[k4 + 3][m] = va.w;
            float4 vb = *(const float4*)(W + (size_t)(col0 + m) * E_ + k0 + k4);
            Bs[k4 + 0][m] = vb.x; Bs[k4 + 1][m] = vb.y;
            Bs[k4 + 2][m] = vb.z; Bs[k4 + 3][m] = vb.w;
        }
        __syncthreads();

        #pragma unroll
        for (int k = 0; k < BK; ++k) {
            float a[8], b[8];
            #pragma unroll
            for (int i = 0; i < 8; ++i) a[i] = As[k][tm + i];
            #pragma unroll
            for (int j = 0; j < 8; ++j) b[j] = Bs[k][tn + j];
            #pragma unroll
            for (int i = 0; i < 8; ++i)
                #pragma unroll
                for (int j = 0; j < 8; ++j)
                    acc[i][j] = fmaf(a[i], b[j], acc[i][j]);
        }
        __syncthreads();
    }

    #pragma unroll
    for (int i = 0; i < 8; ++i) {
        int m = row0 + tm + i;
        float* op = out + (size_t)m * E_ + col0 + tn;
        #pragma unroll
        for (int j = 0; j < 8; ++j)
            op[j] = acc[i][j] + bias[col0 + tn + j];
    }
}

// ---------------------------------------------------------------------------
// Kernel C: in-place LayerNorm + swish over rows of d_out [NT, 512]
// One block (256 threads) per row; each thread owns 2 elements.
// ---------------------------------------------------------------------------
__global__ __launch_bounds__(256) void ln_kernel(const float* __restrict__ gamma,
                                                 const float* __restrict__ beta,
                                                 float* __restrict__ out) {
    int row = blockIdx.x;
    float* p = out + (size_t)row * E_;
    int tid = threadIdx.x;

    float y0 = p[tid], y1 = p[tid + 256];
    float sum = y0 + y1;
    float sq  = y0 * y0 + y1 * y1;

    #pragma unroll
    for (int off = 16; off > 0; off >>= 1) {
        sum += __shfl_xor_sync(0xffffffffu, sum, off);
        sq  += __shfl_xor_sync(0xffffffffu, sq,  off);
    }
    __shared__ float ssum[8], ssq[8];
    int warp = tid >> 5, lane = tid & 31;
    if (lane == 0) { ssum[warp] = sum; ssq[warp] = sq; }
    __syncthreads();
    if (warp == 0) {
        float a  = (lane < 8) ? ssum[lane] : 0.0f;
        float b2 = (lane < 8) ? ssq[lane]  : 0.0f;
        #pragma unroll
        for (int off = 4; off > 0; off >>= 1) {
            a  += __shfl_xor_sync(0xffffffffu, a,  off);
            b2 += __shfl_xor_sync(0xffffffffu, b2, off);
        }
        if (lane == 0) { ssum[0] = a; ssq[0] = b2; }
    }
    __syncthreads();

    float mean = ssum[0] * (1.0f / E_);
    float var  = ssq[0] * (1.0f / E_) - mean * mean;
    float rstd = rsqrtf(var + 1e-5f);

    float o0 = (y0 - mean) * rstd * gamma[tid]       + beta[tid];
    float o1 = (y1 - mean) * rstd * gamma[tid + 256] + beta[tid + 256];
    p[tid]       = o0 / (1.0f + __expf(-o0));
    p[tid + 256] = o1 / (1.0f + __expf(-o1));
}

// ---------------------------------------------------------------------------
extern "C" void kernel_launch(void* const* d_in, const int* in_sizes, int n_in,
                              void* d_out, int out_size) {
    const int*   tokens = (const int*)  d_in[0];
    const float* table  = (const float*)d_in[1];
    const float* pos    = (const float*)d_in[2];
    const float* ffn_w  = (const float*)d_in[3];
    const float* ffn_b  = (const float*)d_in[4];
    const float* ln_g   = (const float*)d_in[5];
    const float* ln_b   = (const float*)d_in[6];
    float* out = (float*)d_out;

    attn_kernel<<<NT / 32, 256>>>(tokens, table, pos);

    dim3 gb(E_ / BN, NT / BM);   // (4, 256)
    ffn_kernel<<<gb, 256>>>(ffn_w, ffn_b, out);

    ln_kernel<<<NT, 256>>>(ln_g, ln_b, out);
}

// round 3
// speedup vs baseline: 2.1972x; 2.1972x over previous
#include <cuda_runtime.h>
#include <cuda_bf16.h>
#include <cstdint>

#define B_  16
#define T_  2048
#define E_  512
#define H_  4
#define C_  3
#define NT  (B_ * T_)   // 32768 tokens

// ---------------------------------------------------------------------------
// Scratch (static device globals — allowed)
// ---------------------------------------------------------------------------
__device__ __nv_bfloat16 g_vhi[(size_t)NT * E_];   // 32 MB
__device__ __nv_bfloat16 g_vlo[(size_t)NT * E_];   // 32 MB
__device__ __nv_bfloat16 g_whi[(size_t)E_ * E_];   // 512 KB
__device__ __nv_bfloat16 g_wlo[(size_t)E_ * E_];

__device__ __forceinline__ uint32_t smem_to_u32(const void* p) {
    uint32_t a;
    asm("{ .reg .u64 t; cvta.to.shared.u64 t, %1; cvt.u32.u64 %0, t; }" : "=r"(a) : "l"(p));
    return a;
}
__device__ __forceinline__ void cp16(uint32_t dst, const void* src) {
    asm volatile("cp.async.cg.shared.global [%0], [%1], 16;" :: "r"(dst), "l"(src));
}
__device__ __forceinline__ void ldm_x4(uint32_t* r, uint32_t addr) {
    asm volatile("ldmatrix.sync.aligned.m8n8.x4.shared.b16 {%0,%1,%2,%3}, [%4];"
                 : "=r"(r[0]), "=r"(r[1]), "=r"(r[2]), "=r"(r[3]) : "r"(addr));
}
__device__ __forceinline__ void mma_bf16(float* d, const uint32_t* a, const uint32_t* b) {
    asm volatile(
        "mma.sync.aligned.m16n8k16.row.col.f32.bf16.bf16.f32 "
        "{%0,%1,%2,%3}, {%4,%5,%6,%7}, {%8,%9}, {%0,%1,%2,%3};"
        : "+f"(d[0]), "+f"(d[1]), "+f"(d[2]), "+f"(d[3])
        : "r"(a[0]), "r"(a[1]), "r"(a[2]), "r"(a[3]), "r"(b[0]), "r"(b[1]));
}

// ---------------------------------------------------------------------------
// Kernel A: embed gather + windowed positional attention -> v (bf16 hi/lo)
// ---------------------------------------------------------------------------
__global__ __launch_bounds__(256) void attn_kernel(const int* __restrict__ tokens,
                                                   const float* __restrict__ table,
                                                   const float* __restrict__ pos) {
    __shared__ float pos_s[H_ * E_ * C_];  // pos[h][e][c]
    int tid = threadIdx.x;
    for (int i = tid; i < H_ * E_ * C_; i += 256) pos_s[i] = pos[i];
    __syncthreads();

    int warp = tid >> 5, lane = tid & 31;
    int base = blockIdx.x * 32 + warp * 4;
    int t0 = base & (T_ - 1);

    float x0[16], x1[16], x2[16];
    if (t0 >= 2) {
        const float* rp = table + (size_t)tokens[base - 2] * E_;
        #pragma unroll
        for (int j = 0; j < 16; ++j) x0[j] = rp[lane + j * 32];
    } else {
        #pragma unroll
        for (int j = 0; j < 16; ++j) x0[j] = 0.0f;
    }
    if (t0 >= 1) {
        const float* rp = table + (size_t)tokens[base - 1] * E_;
        #pragma unroll
        for (int j = 0; j < 16; ++j) x1[j] = rp[lane + j * 32];
    } else {
        #pragma unroll
        for (int j = 0; j < 16; ++j) x1[j] = 0.0f;
    }

    #pragma unroll
    for (int it = 0; it < 4; ++it) {
        int g = base + it;
        {
            const float* rp = table + (size_t)tokens[g] * E_;
            #pragma unroll
            for (int j = 0; j < 16; ++j) x2[j] = rp[lane + j * 32];
        }

        float s[12];
        #pragma unroll
        for (int i = 0; i < 12; ++i) s[i] = 0.0f;
        #pragma unroll
        for (int j = 0; j < 16; ++j) {
            int e = lane + j * 32;
            #pragma unroll
            for (int h = 0; h < 4; ++h) {
                const float* pp = pos_s + h * (E_ * C_) + e * C_;
                s[h * 3 + 0] = fmaf(x0[j], pp[0], s[h * 3 + 0]);
                s[h * 3 + 1] = fmaf(x1[j], pp[1], s[h * 3 + 1]);
                s[h * 3 + 2] = fmaf(x2[j], pp[2], s[h * 3 + 2]);
            }
        }
        #pragma unroll
        for (int off = 16; off > 0; off >>= 1) {
            #pragma unroll
            for (int i = 0; i < 12; ++i)
                s[i] += __shfl_xor_sync(0xffffffffu, s[i], off);
        }
        float c0 = (s[0] + s[3] + s[6] + s[9])  * (1.0f / 12.0f);
        float c1 = (s[1] + s[4] + s[7] + s[10]) * (1.0f / 12.0f);
        float c2 = (s[2] + s[5] + s[8] + s[11]) * (1.0f / 12.0f);

        __nv_bfloat16* ph = g_vhi + (size_t)g * E_;
        __nv_bfloat16* pl = g_vlo + (size_t)g * E_;
        #pragma unroll
        for (int j = 0; j < 16; ++j) {
            float v = c0 * x0[j] + c1 * x1[j] + c2 * x2[j];
            __nv_bfloat16 hi = __float2bfloat16_rn(v);
            __nv_bfloat16 lo = __float2bfloat16_rn(v - __bfloat162float(hi));
            ph[lane + j * 32] = hi;
            pl[lane + j * 32] = lo;
        }
        #pragma unroll
        for (int j = 0; j < 16; ++j) { x0[j] = x1[j]; x1[j] = x2[j]; }
    }
}

// ---------------------------------------------------------------------------
// Kernel W: split ffn_w into bf16 hi/lo
// ---------------------------------------------------------------------------
__global__ __launch_bounds__(256) void wsplit_kernel(const float* __restrict__ W) {
    int i = blockIdx.x * 256 + threadIdx.x;
    float v = W[i];
    __nv_bfloat16 hi = __float2bfloat16_rn(v);
    g_whi[i] = hi;
    g_wlo[i] = __float2bfloat16_rn(v - __bfloat162float(hi));
}

// ---------------------------------------------------------------------------
// Kernel B: HMMA (mma.sync bf16) split GEMM  Y = V @ W^T + bias
// CTA tile 128x128, KBLK=32, 8 warps (warp tile 32x64), cp.async double buffer.
// Smem row pitch 80B (64B data + 16B pad) -> conflict-free ldmatrix.
// ---------------------------------------------------------------------------
#define KBLK   32
#define PITCH  80
#define TILE_B (128 * PITCH)            // 10240 bytes per operand tile
#define STAGE  (4 * TILE_B)             // A_HI, A_LO, B_HI, B_LO
#define SM_GEMM (2 * STAGE)             // 81920 bytes

__global__ __launch_bounds__(256) void gemm_kernel(const float* __restrict__ bias,
                                                   float* __restrict__ out) {
    extern __shared__ char smem[];
    const uint32_t sb = smem_to_u32(smem);

    const int tid  = threadIdx.x;
    const int wid  = tid >> 5, lane = tid & 31;
    const int wm   = wid >> 1;          // 0..3
    const int wn   = wid & 1;           // 0..1
    const int m0   = blockIdx.y * 128;
    const int n0   = blockIdx.x * 128;

    const char* vhi = (const char*)g_vhi;
    const char* vlo = (const char*)g_vlo;
    const char* whi = (const char*)g_whi;
    const char* wlo = (const char*)g_wlo;

    // per-thread cp.async source/dest mapping: 512 chunks of 16B per tile
    // i = tid + it*256 ; row = i>>2, chunk = i&3
    auto issue_stage = [&](int kb) {
        const uint32_t st = sb + (kb & 1) * STAGE;
        const int k0 = kb * KBLK;
        #pragma unroll
        for (int it = 0; it < 2; ++it) {
            int i = tid + it * 256;
            int r = i >> 2, c = i & 3;
            uint32_t so = r * PITCH + c * 16;
            size_t ga = ((size_t)(m0 + r) * E_ + k0 + c * 8) * 2;
            size_t gb = ((size_t)(n0 + r) * E_ + k0 + c * 8) * 2;
            cp16(st + 0 * TILE_B + so, vhi + ga);
            cp16(st + 1 * TILE_B + so, vlo + ga);
            cp16(st + 2 * TILE_B + so, whi + gb);
            cp16(st + 3 * TILE_B + so, wlo + gb);
        }
        asm volatile("cp.async.commit_group;" ::: "memory");
    };

    float d[2][8][4];
    #pragma unroll
    for (int i = 0; i < 2; ++i)
        #pragma unroll
        for (int j = 0; j < 8; ++j)
            #pragma unroll
            for (int q = 0; q < 4; ++q) d[i][j][q] = 0.0f;

    // ldmatrix lane address components (byte offsets within a tile)
    // A: row = (l&7) + ((l>>3)&1)*8, k8sel = l>>4
    const int a_row = (lane & 7) + ((lane >> 3) & 1) * 8;
    const int a_k8  = (lane >> 4);
    // B: row = (l&7) + ((l>>4)&1)*8, k8sel = (l>>3)&1
    const int b_row = (lane & 7) + ((lane >> 4) & 1) * 8;
    const int b_k8  = (lane >> 3) & 1;

    issue_stage(0);
    issue_stage(1);

    const int NKB = E_ / KBLK;   // 16
    for (int kb = 0; kb < NKB; ++kb) {
        if (kb < NKB - 1)
            asm volatile("cp.async.wait_group 1;" ::: "memory");
        else
            asm volatile("cp.async.wait_group 0;" ::: "memory");
        __syncthreads();

        const uint32_t st = sb + (kb & 1) * STAGE;
        const uint32_t aH = st + 0 * TILE_B;
        const uint32_t aL = st + 1 * TILE_B;
        const uint32_t bH = st + 2 * TILE_B;
        const uint32_t bL = st + 3 * TILE_B;

        #pragma unroll
        for (int kk = 0; kk < 2; ++kk) {
            uint32_t ah[2][4], al[2][4];
            #pragma unroll
            for (int mi = 0; mi < 2; ++mi) {
                uint32_t off = (uint32_t)(wm * 32 + mi * 16 + a_row) * PITCH
                             + kk * 32 + a_k8 * 16;
                ldm_x4(ah[mi], aH + off);
                ldm_x4(al[mi], aL + off);
            }
            #pragma unroll
            for (int ni = 0; ni < 4; ++ni) {
                uint32_t off = (uint32_t)(wn * 64 + ni * 16 + b_row) * PITCH
                             + kk * 32 + b_k8 * 16;
                uint32_t bh[4], bl[4];
                ldm_x4(bh, bH + off);
                ldm_x4(bl, bL + off);
                #pragma unroll
                for (int mi = 0; mi < 2; ++mi) {
                    mma_bf16(d[mi][ni * 2 + 0], ah[mi], bh + 0);
                    mma_bf16(d[mi][ni * 2 + 1], ah[mi], bh + 2);
                    mma_bf16(d[mi][ni * 2 + 0], ah[mi], bl + 0);
                    mma_bf16(d[mi][ni * 2 + 1], ah[mi], bl + 2);
                    mma_bf16(d[mi][ni * 2 + 0], al[mi], bh + 0);
                    mma_bf16(d[mi][ni * 2 + 1], al[mi], bh + 2);
                }
            }
        }
        __syncthreads();
        if (kb + 2 < NKB) issue_stage(kb + 2);
    }

    // Epilogue: + bias, write out
    const int g = lane >> 2, t = lane & 3;
    #pragma unroll
    for (int mi = 0; mi < 2; ++mi) {
        #pragma unroll
        for (int ni = 0; ni < 4; ++ni) {
            #pragma unroll
            for (int h = 0; h < 2; ++h) {
                int col = n0 + wn * 64 + ni * 16 + h * 8 + t * 2;
                float b0 = __ldg(bias + col), b1 = __ldg(bias + col + 1);
                int row = m0 + wm * 32 + mi * 16 + g;
                float* o0 = out + (size_t)row * E_ + col;
                float* o1 = out + (size_t)(row + 8) * E_ + col;
                const float* dd = d[mi][ni * 2 + h];
                o0[0] = dd[0] + b0; o0[1] = dd[1] + b1;
                o1[0] = dd[2] + b0; o1[1] = dd[3] + b1;
            }
        }
    }
}

// ---------------------------------------------------------------------------
// Kernel C: in-place LayerNorm + swish (one block per row)
// ---------------------------------------------------------------------------
__global__ __launch_bounds__(256) void ln_kernel(const float* __restrict__ gamma,
                                                 const float* __restrict__ beta,
                                                 float* __restrict__ out) {
    int row = blockIdx.x;
    float* p = out + (size_t)row * E_;
    int tid = threadIdx.x;

    float y0 = p[tid], y1 = p[tid + 256];
    float sum = y0 + y1;
    float sq  = y0 * y0 + y1 * y1;

    #pragma unroll
    for (int off = 16; off > 0; off >>= 1) {
        sum += __shfl_xor_sync(0xffffffffu, sum, off);
        sq  += __shfl_xor_sync(0xffffffffu, sq,  off);
    }
    __shared__ float ssum[8], ssq[8];
    int warp = tid >> 5, lane = tid & 31;
    if (lane == 0) { ssum[warp] = sum; ssq[warp] = sq; }
    __syncthreads();
    if (warp == 0) {
        float a  = (lane < 8) ? ssum[lane] : 0.0f;
        float b2 = (lane < 8) ? ssq[lane]  : 0.0f;
        #pragma unroll
        for (int off = 4; off > 0; off >>= 1) {
            a  += __shfl_xor_sync(0xffffffffu, a,  off);
            b2 += __shfl_xor_sync(0xffffffffu, b2, off);
        }
        if (lane == 0) { ssum[0] = a; ssq[0] = b2; }
    }
    __syncthreads();

    float mean = ssum[0] * (1.0f / E_);
    float var  = ssq[0] * (1.0f / E_) - mean * mean;
    float rstd = rsqrtf(var + 1e-5f);

    float o0 = (y0 - mean) * rstd * gamma[tid]       + beta[tid];
    float o1 = (y1 - mean) * rstd * gamma[tid + 256] + beta[tid + 256];
    p[tid]       = o0 / (1.0f + __expf(-o0));
    p[tid + 256] = o1 / (1.0f + __expf(-o1));
}

// ---------------------------------------------------------------------------
extern "C" void kernel_launch(void* const* d_in, const int* in_sizes, int n_in,
                              void* d_out, int out_size) {
    const int*   tokens = (const int*)  d_in[0];
    const float* table  = (const float*)d_in[1];
    const float* pos    = (const float*)d_in[2];
    const float* ffn_w  = (const float*)d_in[3];
    const float* ffn_b  = (const float*)d_in[4];
    const float* ln_g   = (const float*)d_in[5];
    const float* ln_b   = (const float*)d_in[6];
    float* out = (float*)d_out;

    cudaFuncSetAttribute(gemm_kernel, cudaFuncAttributeMaxDynamicSharedMemorySize, SM_GEMM);

    attn_kernel<<<NT / 32, 256>>>(tokens, table, pos);
    wsplit_kernel<<<(E_ * E_) / 256, 256>>>(ffn_w);
    dim3 gg(E_ / 128, NT / 128);   // (4, 256)
    gemm_kernel<<<gg, 256, SM_GEMM>>>(ffn_b, out);
    ln_kernel<<<NT, 256>>>(ln_g, ln_b, out);
}